// round 12
// baseline (speedup 1.0000x reference)
#include <cuda_runtime.h>
#include <cuda_fp16.h>
#include <cstdint>

#define EPS 1e-5f
#define B_  4
#define N_  512
#define M_  512
#define D_  128
#define H_  128
#define TN 4
#define TM 32
#define NTILES 8192          // 4 * 128 * 16
#define GRID 148
#define THREADS 256

// SMEM byte offsets
#define SM_W    0                      // fp16 W1d^T [h][k], swizzled, 32768 B (init only)
#define SM_XS   32768                  // fp16 x:  2 x 4*128*2  = 2 x 1024
#define SM_YS   (SM_XS + 2048)         // fp16 y:  2 x 32*136*2 = 2 x 8704
#define SM_XWS  (SM_YS + 17408)        // fp32 xw: 2 x 4*128*4  = 2 x 2048
#define SM_YWS  (SM_XWS + 4096)        // fp32 yw: 2 x 32*136*4 = 2 x 17408
#define SM_GAM  (SM_YWS + 34816)
#define SM_BET  (SM_GAM + 512)
#define SM_W2   (SM_BET + 512)
#define SM_RED1 (SM_W2 + 512)          // 256 floats
#define SM_RED2 (SM_RED1 + 1024)       // 256 floats
#define SM_O2   (SM_RED2 + 1024)       // 256 floats
#define SMEM_BYTES (SM_O2 + 1024)

#define YSTRIDE   136  // fp32 yw rows: floats per row
#define YSTRIDE_H 136  // fp16 y rows: halves per row

__device__ __forceinline__ uint32_t smem_u32(const void* p) {
    uint32_t a;
    asm("{ .reg .u64 t; cvta.to.shared.u64 t, %1; cvt.u32.u64 %0, t; }" : "=r"(a) : "l"(p));
    return a;
}
__device__ __forceinline__ void ldsm4(uint32_t* r, uint32_t addr) {
    asm volatile("ldmatrix.sync.aligned.m8n8.x4.shared.b16 {%0,%1,%2,%3}, [%4];"
        : "=r"(r[0]), "=r"(r[1]), "=r"(r[2]), "=r"(r[3]) : "r"(addr));
}
__device__ __forceinline__ void mma16816(float* c, const uint32_t* a,
                                         uint32_t b0, uint32_t b1) {
    asm volatile("mma.sync.aligned.m16n8k16.row.col.f32.f16.f16.f32 "
        "{%0,%1,%2,%3}, {%4,%5,%6,%7}, {%8,%9}, {%0,%1,%2,%3};"
        : "+f"(c[0]), "+f"(c[1]), "+f"(c[2]), "+f"(c[3])
        : "r"(a[0]), "r"(a[1]), "r"(a[2]), "r"(a[3]), "r"(b0), "r"(b1));
}
// swizzled offset into a [rows][128] fp16 tile (256 B/row, 16B-chunk XOR swizzle)
__device__ __forceinline__ uint32_t woff(int r, int k) {
    return (uint32_t)(r * 256 + ((((k >> 3) ^ (r & 7)) << 4)) + (k & 7) * 2);
}
__device__ __forceinline__ uint32_t h2u(__half2 h) {
    return *reinterpret_cast<uint32_t*>(&h);
}

// Scratch: xw = x@W1x + b1 (b1 ONLY here), yw = y@W1y
__device__ float g_xw[B_ * N_ * H_];
__device__ float g_yw[B_ * M_ * H_];

// ---------------------------------------------------------------------------
// Kernel 1: precompute xw/yw (fp32 exact)
// ---------------------------------------------------------------------------
__global__ __launch_bounds__(128) void precompute_kernel(
    const float* __restrict__ x, const float* __restrict__ y,
    const float* __restrict__ W1, const float* __restrict__ b1)
{
    const bool isY = blockIdx.x >= 256;
    const int r0 = (isY ? blockIdx.x - 256 : blockIdx.x) * 8;
    const float* __restrict__ src = isY ? y : x;
    const float* __restrict__ W = W1 + (isY ? D_ * H_ : 0);
    float* __restrict__ dst = isY ? g_yw : g_xw;

    __shared__ float v[8][D_];
    const int h = threadIdx.x;
    #pragma unroll
    for (int r = 0; r < 8; r++) v[r][h] = src[(r0 + r) * D_ + h];
    __syncthreads();

    float acc[8];
    const float bb = isY ? 0.f : b1[h];
    #pragma unroll
    for (int r = 0; r < 8; r++) acc[r] = bb;
    #pragma unroll 4
    for (int d = 0; d < D_; d++) {
        const float w = W[d * H_ + h];
        #pragma unroll
        for (int r = 0; r < 8; r++) acc[r] = fmaf(v[r][d], w, acc[r]);
    }
    #pragma unroll
    for (int r = 0; r < 8; r++) dst[(r0 + r) * H_ + h] = acc[r];
}

// ---------------------------------------------------------------------------
// Kernel 2: persistent HMMA kernel with register-resident W fragments.
// Tile = 128 pairs (4n x 32m) x 128 h, K = 128. 8 warps:
// warp w -> n-row (w&3), h-half (w>>2)*64. W B-fragments for the warp's
// h-half, all K, live in 128 registers for the whole kernel -> NO LDSM
// in the mainloop. acc = 64 regs/thread.
// ---------------------------------------------------------------------------
__global__ void __launch_bounds__(THREADS, 1) main_kernel(
    const float* __restrict__ x, const float* __restrict__ y,
    const float* __restrict__ W1,
    const float* __restrict__ gamma, const float* __restrict__ beta,
    const float* __restrict__ W2, const float* __restrict__ b2,
    float* __restrict__ out)
{
    extern __shared__ char sm[];
    const int tid = threadIdx.x;
    const int wid = tid >> 5, lane = tid & 31;
    const int nw = wid & 3;          // n-row within tile
    const int hh = wid >> 2;         // h-half (0 or 1)
    const int q = lane >> 2, c = lane & 3;

    // ---- one-time: W1d -> fp16 Wsm[h][k] swizzled ----
    {
        __half* wp = (__half*)sm;
        #pragma unroll
        for (int i = 0; i < 64; i++) {
            int e = i * 256 + tid;           // 16384 elements
            int k = e >> 7, h = e & 127;
            float v = W1[(2 * D_ + k) * H_ + h];
            *reinterpret_cast<__half*>((char*)wp + woff(h, k)) = __float2half_rn(v);
        }
    }
    if (tid < 128) {
        ((float*)(sm + SM_GAM))[tid] = gamma[tid];
        ((float*)(sm + SM_BET))[tid] = beta[tid];
        ((float*)(sm + SM_W2))[tid]  = W2[tid];
    }
    const float bias2 = b2[0];
    __syncthreads();

    // ---- one-time: pull this warp's W fragments into registers ----
    const uint32_t wbase = smem_u32(sm);
    const int rp  = (((lane >> 4) & 1) << 3) + (lane & 7);
    const int kb8 = (lane >> 3) & 1;
    const int l7  = lane & 7;
    uint32_t brp[8][4][4];   // [kt][nt2-in-half][frag] = 128 regs, persistent
    #pragma unroll
    for (int kt = 0; kt < 8; kt++) {
        const uint32_t kcol = (uint32_t)((((2 * kt + kb8) ^ l7) << 4));
        #pragma unroll
        for (int j = 0; j < 4; j++) {
            uint32_t addr = wbase + (uint32_t)(((hh * 4 + j) * 16 + rp) * 256) + kcol;
            ldsm4(brp[kt][j], addr);
        }
    }

    float* SRED1 = (float*)(sm + SM_RED1);
    float* SRED2 = (float*)(sm + SM_RED2);
    float* SO2   = (float*)(sm + SM_O2);

    // tile loader: LDG fp32, convert, STS fp16 (x/y) + fp32 (xw/yw)
    auto load_tile = [&](int t, int sb) {
        const int bt = t >> 11, rem = t & 2047;
        const int n0 = (rem >> 4) * TN, m0 = (rem & 15) * TM;
        if (tid < 128) {
            float4 v = ((const float4*)(x + (bt * N_ + n0) * D_))[tid];
            __half2 h0 = __floats2half2_rn(v.x, v.y);
            __half2 h1 = __floats2half2_rn(v.z, v.w);
            uint2 pk = make_uint2(h2u(h0), h2u(h1));
            *(uint2*)((char*)sm + SM_XS + sb * 1024 + tid * 8) = pk;
            ((float4*)(sm + SM_XWS + sb * 2048))[tid] =
                ((const float4*)(g_xw + (bt * N_ + n0) * H_))[tid];
        }
        {
            const float* yg = y + (bt * M_ + m0) * D_;
            __half* ysb = (__half*)(sm + SM_YS + sb * 8704);
            const float* ywg = g_yw + (bt * M_ + m0) * H_;
            float* ywsb = (float*)(sm + SM_YWS + sb * 17408);
            #pragma unroll
            for (int j = 0; j < 4; j++) {
                int e = j * 256 + tid;
                int r = e >> 5, c4 = (e & 31) * 4;
                float4 v = *(const float4*)(yg + r * 128 + c4);
                __half2 h0 = __floats2half2_rn(v.x, v.y);
                __half2 h1 = __floats2half2_rn(v.z, v.w);
                uint2 pk = make_uint2(h2u(h0), h2u(h1));
                *(uint2*)(ysb + r * YSTRIDE_H + c4) = pk;
                *(float4*)(ywsb + r * YSTRIDE + c4) = *(const float4*)(ywg + r * 128 + c4);
            }
        }
    };

    load_tile(blockIdx.x, 0);
    __syncthreads();

    int iter = 0;
    for (int t = blockIdx.x; t < NTILES; t += GRID, iter++) {
        const int sb = iter & 1;
        const int bt = t >> 11, rem = t & 2047;
        const int n0 = (rem >> 4) * TN, m0 = (rem & 15) * TM;

        float acc[2][8][4];
        #pragma unroll
        for (int s = 0; s < 2; s++)
            #pragma unroll
            for (int i = 0; i < 8; i++)
                #pragma unroll
                for (int j = 0; j < 4; j++) acc[s][i][j] = 0.f;

        const __half* xr  = (const __half*)(sm + SM_XS + sb * 1024) + nw * 128;
        const __half* yr0 = (const __half*)(sm + SM_YS + sb * 8704) + q * YSTRIDE_H;

        #pragma unroll
        for (int kt = 0; kt < 8; kt++) {
            const int k0 = kt * 16 + 2 * c;
            // ---- A-gen: half2 |x - y| fragments, both m16 sets ----
            uint32_t af[2][4];
            {
                __half2 x0 = *(const __half2*)(xr + k0);
                __half2 x1 = *(const __half2*)(xr + k0 + 8);
                #pragma unroll
                for (int s = 0; s < 2; s++) {
                    const __half* ya = yr0 + (16 * s) * YSTRIDE_H;
                    const __half* yb = ya + 8 * YSTRIDE_H;
                    __half2 a0 = *(const __half2*)(ya + k0);
                    __half2 a1 = *(const __half2*)(ya + k0 + 8);
                    __half2 b0 = *(const __half2*)(yb + k0);
                    __half2 b1 = *(const __half2*)(yb + k0 + 8);
                    af[s][0] = h2u(__habs2(__hsub2(x0, a0)));
                    af[s][1] = h2u(__habs2(__hsub2(x0, b0)));
                    af[s][2] = h2u(__habs2(__hsub2(x1, a1)));
                    af[s][3] = h2u(__habs2(__hsub2(x1, b1)));
                }
            }
            // ---- HMMA: pure register-fed, no LDSM ----
            #pragma unroll
            for (int j = 0; j < 4; j++) {
                mma16816(acc[0][2*j],   af[0], brp[kt][j][0], brp[kt][j][1]);
                mma16816(acc[0][2*j+1], af[0], brp[kt][j][2], brp[kt][j][3]);
                mma16816(acc[1][2*j],   af[1], brp[kt][j][0], brp[kt][j][1]);
                mma16816(acc[1][2*j+1], af[1], brp[kt][j][2], brp[kt][j][3]);
            }
        }

        // ---- prefetch next tile (other buffer) ----
        if (t + GRID < NTILES) load_tile(t + GRID, sb ^ 1);

        // ---- epilogue pass 1: add xw+yw in place, partial LN sums ----
        const float* xwr = (const float*)(sm + SM_XWS + sb * 2048) + nw * 128;
        const float* ywr = (const float*)(sm + SM_YWS + sb * 17408) + q * YSTRIDE;
        {
            float s1[4] = {0.f, 0.f, 0.f, 0.f};
            float s2[4] = {0.f, 0.f, 0.f, 0.f};
            #pragma unroll
            for (int nt = 0; nt < 8; nt++) {
                const int h = hh * 64 + nt * 8 + 2 * c;
                float2 xw2 = *(const float2*)(xwr + h);
                #pragma unroll
                for (int g = 0; g < 4; g++) {
                    const int s = g >> 1, hi = (g & 1) << 1;
                    float2 yw2 = *(const float2*)(ywr + 8 * g * YSTRIDE + h);
                    float v0 = acc[s][nt][hi]     + xw2.x + yw2.x;
                    float v1 = acc[s][nt][hi + 1] + xw2.y + yw2.y;
                    acc[s][nt][hi] = v0; acc[s][nt][hi + 1] = v1;
                    s1[g] += v0 + v1;
                    s2[g] = fmaf(v0, v0, fmaf(v1, v1, s2[g]));
                }
            }
            #pragma unroll
            for (int g = 0; g < 4; g++) {
                #pragma unroll
                for (int o = 1; o <= 2; o <<= 1) {
                    s1[g] += __shfl_xor_sync(0xffffffffu, s1[g], o);
                    s2[g] += __shfl_xor_sync(0xffffffffu, s2[g], o);
                }
                if (c == 0) {
                    const int idx = ((hh * 4 + nw) * 4 + g) * 8 + q;
                    SRED1[idx] = s1[g];
                    SRED2[idx] = s2[g];
                }
            }
        }
        __syncthreads();   // partials visible

        // ---- combine halves -> mu/rs; pass 2: partial o2 ----
        {
            float mu[4], rs[4], o2[4];
            #pragma unroll
            for (int g = 0; g < 4; g++) {
                const int i0 = ((0 * 4 + nw) * 4 + g) * 8 + q;
                const int i1 = ((1 * 4 + nw) * 4 + g) * 8 + q;
                float s1t = SRED1[i0] + SRED1[i1];
                float s2t = SRED2[i0] + SRED2[i1];
                mu[g] = s1t * (1.f / 128.f);
                rs[g] = rsqrtf(s2t * (1.f / 128.f) - mu[g] * mu[g] + EPS);
                o2[g] = 0.f;
            }
            const float* gm  = (const float*)(sm + SM_GAM);
            const float* be  = (const float*)(sm + SM_BET);
            const float* w2s = (const float*)(sm + SM_W2);
            #pragma unroll
            for (int nt = 0; nt < 8; nt++) {
                const int h = hh * 64 + nt * 8 + 2 * c;
                float2 g2  = *(const float2*)(gm + h);
                float2 be2 = *(const float2*)(be + h);
                float2 w22 = *(const float2*)(w2s + h);
                #pragma unroll
                for (int g = 0; g < 4; g++) {
                    const int s = g >> 1, hi = (g & 1) << 1;
                    float tv;
                    tv = fmaf((acc[s][nt][hi] - mu[g]) * rs[g], g2.x, be2.x);
                    o2[g] = fmaf(fmaxf(tv, 0.f), w22.x, o2[g]);
                    tv = fmaf((acc[s][nt][hi + 1] - mu[g]) * rs[g], g2.y, be2.y);
                    o2[g] = fmaf(fmaxf(tv, 0.f), w22.y, o2[g]);
                }
            }
            #pragma unroll
            for (int g = 0; g < 4; g++) {
                #pragma unroll
                for (int o = 1; o <= 2; o <<= 1)
                    o2[g] += __shfl_xor_sync(0xffffffffu, o2[g], o);
                if (c == 0)
                    SO2[((hh * 4 + nw) * 4 + g) * 8 + q] = o2[g];
            }
            __syncthreads();   // o2 partials visible

            if (hh == 0 && c == 0) {
                const int row = (bt * N_ + n0 + nw) * M_ + m0;
                #pragma unroll
                for (int g = 0; g < 4; g++) {
                    float of = o2[g] + SO2[((4 + nw) * 4 + g) * 8 + q];
                    out[row + q + 8 * g] = fmaxf(of + bias2, 0.f);
                }
            }
        }
    }
}

// ---------------------------------------------------------------------------
extern "C" void kernel_launch(void* const* d_in, const int* in_sizes, int n_in,
                              void* d_out, int out_size)
{
    const float* x     = (const float*)d_in[0];
    const float* y     = (const float*)d_in[1];
    const float* W1    = (const float*)d_in[2];
    const float* b1    = (const float*)d_in[3];
    const float* gamma = (const float*)d_in[4];
    const float* beta  = (const float*)d_in[5];
    const float* W2    = (const float*)d_in[6];
    const float* b2    = (const float*)d_in[7];
    float* out = (float*)d_out;

    cudaFuncSetAttribute(main_kernel,
                         cudaFuncAttributeMaxDynamicSharedMemorySize, SMEM_BYTES);

    precompute_kernel<<<512, 128>>>(x, y, W1, b1);
    main_kernel<<<GRID, THREADS, SMEM_BYTES>>>(x, y, W1, gamma, beta, W2, b2, out);
}

// round 16
// speedup vs baseline: 1.2319x; 1.2319x over previous
#include <cuda_runtime.h>
#include <cuda_fp16.h>
#include <cstdint>

#define EPS 1e-5f
#define B_  4
#define N_  512
#define M_  512
#define D_  128
#define H_  128
#define TN 8
#define TM 32
#define NTILES 4096          // 4 * 64 * 16
#define GRID 148
#define THREADS 256

// SMEM byte offsets
#define SM_W    0                      // fp16 W1d^T [h][k], swizzled, 32768 B
#define SM_XS   32768                  // fp16 x: 2 x 8*128*2   = 2 x 2048
#define SM_YS   (SM_XS + 4096)         // fp16 y: 2 x 32*136*2  = 2 x 8704
#define SM_XWS  (SM_YS + 17408)        // fp32:   2 x 4096
#define SM_YWS  (SM_XWS + 8192)        // fp32:   2 x 17408
#define SM_GAM  (SM_YWS + 34816)
#define SM_BET  (SM_GAM + 512)
#define SM_W2   (SM_BET + 512)
#define SMEM_BYTES (SM_W2 + 512)

#define YSTRIDE  136   // fp32 yw rows: floats per row
#define YSTRIDE_H 136  // fp16 y rows: halves per row

__device__ __forceinline__ uint32_t smem_u32(const void* p) {
    uint32_t a;
    asm("{ .reg .u64 t; cvta.to.shared.u64 t, %1; cvt.u32.u64 %0, t; }" : "=r"(a) : "l"(p));
    return a;
}
__device__ __forceinline__ void ldsm4(uint32_t* r, uint32_t addr) {
    asm volatile("ldmatrix.sync.aligned.m8n8.x4.shared.b16 {%0,%1,%2,%3}, [%4];"
        : "=r"(r[0]), "=r"(r[1]), "=r"(r[2]), "=r"(r[3]) : "r"(addr));
}
__device__ __forceinline__ void mma16816(float* c, const uint32_t* a,
                                         uint32_t b0, uint32_t b1) {
    asm volatile("mma.sync.aligned.m16n8k16.row.col.f32.f16.f16.f32 "
        "{%0,%1,%2,%3}, {%4,%5,%6,%7}, {%8,%9}, {%0,%1,%2,%3};"
        : "+f"(c[0]), "+f"(c[1]), "+f"(c[2]), "+f"(c[3])
        : "r"(a[0]), "r"(a[1]), "r"(a[2]), "r"(a[3]), "r"(b0), "r"(b1));
}
// swizzled offset into a [rows][128] fp16 tile (256 B/row, 16B-chunk XOR swizzle)
__device__ __forceinline__ uint32_t woff(int r, int k) {
    return (uint32_t)(r * 256 + ((((k >> 3) ^ (r & 7)) << 4)) + (k & 7) * 2);
}
__device__ __forceinline__ uint32_t h2u(__half2 h) {
    return *reinterpret_cast<uint32_t*>(&h);
}

// Scratch: xw = x@W1x + b1 (b1 ONLY here), yw = y@W1y
__device__ float g_xw[B_ * N_ * H_];
__device__ float g_yw[B_ * M_ * H_];

// ---------------------------------------------------------------------------
// Kernel 1: precompute xw/yw (fp32 exact)
// ---------------------------------------------------------------------------
__global__ __launch_bounds__(128) void precompute_kernel(
    const float* __restrict__ x, const float* __restrict__ y,
    const float* __restrict__ W1, const float* __restrict__ b1)
{
    const bool isY = blockIdx.x >= 256;
    const int r0 = (isY ? blockIdx.x - 256 : blockIdx.x) * 8;
    const float* __restrict__ src = isY ? y : x;
    const float* __restrict__ W = W1 + (isY ? D_ * H_ : 0);
    float* __restrict__ dst = isY ? g_yw : g_xw;

    __shared__ float v[8][D_];
    const int h = threadIdx.x;
    #pragma unroll
    for (int r = 0; r < 8; r++) v[r][h] = src[(r0 + r) * D_ + h];
    __syncthreads();

    float acc[8];
    const float bb = isY ? 0.f : b1[h];
    #pragma unroll
    for (int r = 0; r < 8; r++) acc[r] = bb;
    #pragma unroll 4
    for (int d = 0; d < D_; d++) {
        const float w = W[d * H_ + h];
        #pragma unroll
        for (int r = 0; r < 8; r++) acc[r] = fmaf(v[r][d], w, acc[r]);
    }
    #pragma unroll
    for (int r = 0; r < 8; r++) dst[(r0 + r) * H_ + h] = acc[r];
}

// ---------------------------------------------------------------------------
// Kernel 2: persistent HMMA kernel, software-pipelined mainloop.
// Tile = 256 pairs (8n x 32m) x 128 h, K = 128. x/y staged in SMEM as fp16;
// A-gen is pure half2 (HSUB2 + HABS2). Each LDSM'd B fragment feeds 4 HMMAs.
// ---------------------------------------------------------------------------
__global__ void __launch_bounds__(THREADS, 1) main_kernel(
    const float* __restrict__ x, const float* __restrict__ y,
    const float* __restrict__ W1,
    const float* __restrict__ gamma, const float* __restrict__ beta,
    const float* __restrict__ W2, const float* __restrict__ b2,
    float* __restrict__ out)
{
    extern __shared__ char sm[];
    const int tid = threadIdx.x;
    const int wid = tid >> 5, lane = tid & 31;
    const int q = lane >> 2, c = lane & 3;

    // ---- one-time: W1d -> fp16 Wsm[h][k] swizzled ----
    {
        __half* wp = (__half*)sm;
        #pragma unroll
        for (int i = 0; i < 64; i++) {
            int e = i * 256 + tid;
            int k = e >> 7, h = e & 127;
            float v = W1[(2 * D_ + k) * H_ + h];
            *reinterpret_cast<__half*>((char*)wp + woff(h, k)) = __float2half_rn(v);
        }
    }
    if (tid < 128) {
        ((float*)(sm + SM_GAM))[tid] = gamma[tid];
        ((float*)(sm + SM_BET))[tid] = beta[tid];
        ((float*)(sm + SM_W2))[tid]  = W2[tid];
    }
    const float bias2 = b2[0];

    // per-lane ldmatrix B addressing constants
    const uint32_t wbase = smem_u32(sm);
    const int rp  = (((lane >> 4) & 1) << 3) + (lane & 7);
    const int kb8 = (lane >> 3) & 1;
    const int l7  = lane & 7;

    // tile loader: LDG fp32, convert, STS fp16 (x/y) + fp32 (xw/yw)
    // y/yw: 32 rows x 128 cols -> 1024 vector stores each -> j<4 with 256 thr
    auto load_tile = [&](int t, int sb) {
        const int bt = t >> 10, rem = t & 1023;
        const int n0 = (rem >> 4) * TN, m0 = (rem & 15) * TM;
        {
            float4 v = ((const float4*)(x + (bt * N_ + n0) * D_))[tid];
            __half2 h0 = __floats2half2_rn(v.x, v.y);
            __half2 h1 = __floats2half2_rn(v.z, v.w);
            uint2 pk = make_uint2(h2u(h0), h2u(h1));
            *(uint2*)((char*)sm + SM_XS + sb * 2048 + tid * 8) = pk;
        }
        ((float4*)(sm + SM_XWS + sb * 4096))[tid] =
            ((const float4*)(g_xw + (bt * N_ + n0) * H_))[tid];
        {
            const float* yg = y + (bt * M_ + m0) * D_;
            __half* ysb = (__half*)(sm + SM_YS + sb * 8704);
            #pragma unroll
            for (int j = 0; j < 4; j++) {
                int e = j * 256 + tid;
                int r = e >> 5, c4 = (e & 31) * 4;
                float4 v = *(const float4*)(yg + r * 128 + c4);
                __half2 h0 = __floats2half2_rn(v.x, v.y);
                __half2 h1 = __floats2half2_rn(v.z, v.w);
                uint2 pk = make_uint2(h2u(h0), h2u(h1));
                *(uint2*)(ysb + r * YSTRIDE_H + c4) = pk;
            }
        }
        {
            const float* ywg = g_yw + (bt * M_ + m0) * H_;
            float* ywsb = (float*)(sm + SM_YWS + sb * 17408);
            #pragma unroll
            for (int j = 0; j < 4; j++) {
                int e = j * 256 + tid;
                int r = e >> 5, c4 = (e & 31) * 4;
                *(float4*)(ywsb + r * YSTRIDE + c4) = *(const float4*)(ywg + r * 128 + c4);
            }
        }
    };

    load_tile(blockIdx.x, 0);
    __syncthreads();

    int iter = 0;
    for (int t = blockIdx.x; t < NTILES; t += GRID, iter++) {
        const int sb = iter & 1;
        const int bt = t >> 10, rem = t & 1023;
        const int n0 = (rem >> 4) * TN, m0 = (rem & 15) * TM;

        float acc[2][16][4];
        #pragma unroll
        for (int s = 0; s < 2; s++)
            #pragma unroll
            for (int i = 0; i < 16; i++)
                #pragma unroll
                for (int j = 0; j < 4; j++) acc[s][i][j] = 0.f;

        const __half* xr  = (const __half*)(sm + SM_XS + sb * 2048) + wid * 128;
        const __half* yr0 = (const __half*)(sm + SM_YS + sb * 8704) + q * YSTRIDE_H;

        // A-fragment generator for one kt into af[2][4]
        auto agen = [&](int kt, uint32_t af[2][4]) {
            const int k0 = kt * 16 + 2 * c;
            __half2 x0 = *(const __half2*)(xr + k0);
            __half2 x1 = *(const __half2*)(xr + k0 + 8);
            #pragma unroll
            for (int s = 0; s < 2; s++) {
                const __half* ya = yr0 + (16 * s) * YSTRIDE_H;
                const __half* yb = ya + 8 * YSTRIDE_H;
                __half2 a0 = *(const __half2*)(ya + k0);
                __half2 a1 = *(const __half2*)(ya + k0 + 8);
                __half2 b0 = *(const __half2*)(yb + k0);
                __half2 b1 = *(const __half2*)(yb + k0 + 8);
                af[s][0] = h2u(__habs2(__hsub2(x0, a0)));
                af[s][1] = h2u(__habs2(__hsub2(x0, b0)));
                af[s][2] = h2u(__habs2(__hsub2(x1, a1)));
                af[s][3] = h2u(__habs2(__hsub2(x1, b1)));
            }
        };
        // LDSM chunk: 4 consecutive nt2 fragments (half = 0 or 1) of one kt
        auto ldsm_chunk = [&](uint32_t br[4][4], int kt, int half) {
            const uint32_t kcol = (uint32_t)((((2 * kt + kb8) ^ l7) << 4));
            #pragma unroll
            for (int j = 0; j < 4; j++) {
                uint32_t addr = wbase + (uint32_t)(((half * 4 + j) * 16 + rp) * 256) + kcol;
                ldsm4(br[j], addr);
            }
        };

        uint32_t af[2][2][4];   // [kt&1][m-set][frag]
        uint32_t br[2][4][4];   // [chunk buf][nt2-in-chunk][frag]

        agen(0, af[0]);
        ldsm_chunk(br[0], 0, 0);

        #pragma unroll
        for (int kt = 0; kt < 8; kt++) {
            const int cb = kt & 1;
            // prefetch second half of this kt's B
            ldsm_chunk(br[1], kt, 1);
            // HMMA on first half (br[0] = nt2 0..3)
            #pragma unroll
            for (int j = 0; j < 4; j++) {
                mma16816(acc[0][2*j],   af[cb][0], br[0][j][0], br[0][j][1]);
                mma16816(acc[0][2*j+1], af[cb][0], br[0][j][2], br[0][j][3]);
                mma16816(acc[1][2*j],   af[cb][1], br[0][j][0], br[0][j][1]);
                mma16816(acc[1][2*j+1], af[cb][1], br[0][j][2], br[0][j][3]);
            }
            // under those HMMAs: next kt's A fragments + first B chunk
            if (kt < 7) {
                agen(kt + 1, af[cb ^ 1]);
                ldsm_chunk(br[0], kt + 1, 0);
            }
            // HMMA on second half (br[1] = nt2 4..7)
            #pragma unroll
            for (int j = 0; j < 4; j++) {
                const int n2 = j + 4;
                mma16816(acc[0][2*n2],   af[cb][0], br[1][j][0], br[1][j][1]);
                mma16816(acc[0][2*n2+1], af[cb][0], br[1][j][2], br[1][j][3]);
                mma16816(acc[1][2*n2],   af[cb][1], br[1][j][0], br[1][j][1]);
                mma16816(acc[1][2*n2+1], af[cb][1], br[1][j][2], br[1][j][3]);
            }
        }

        // ---- prefetch next tile (other buffer) ----
        if (t + GRID < NTILES) load_tile(t + GRID, sb ^ 1);

        // ---- epilogue: two passes, acc updated in place ----
        {
            const float* xwr = (const float*)(sm + SM_XWS + sb * 4096) + wid * 128;
            const float* ywr = (const float*)(sm + SM_YWS + sb * 17408) + q * YSTRIDE;
            const float* gm  = (const float*)(sm + SM_GAM);
            const float* be  = (const float*)(sm + SM_BET);
            const float* w2s = (const float*)(sm + SM_W2);
            const int row = (bt * N_ + n0 + wid) * M_ + m0;

            float s1[4] = {0.f, 0.f, 0.f, 0.f};
            float s2[4] = {0.f, 0.f, 0.f, 0.f};
            #pragma unroll
            for (int nt = 0; nt < 16; nt++) {
                const int h = nt * 8 + 2 * c;
                float2 xw2 = *(const float2*)(xwr + h);
                #pragma unroll
                for (int g = 0; g < 4; g++) {
                    const int s = g >> 1, hi = (g & 1) << 1;
                    float2 yw2 = *(const float2*)(ywr + 8 * g * YSTRIDE + h);
                    float v0 = acc[s][nt][hi]     + xw2.x + yw2.x;
                    float v1 = acc[s][nt][hi + 1] + xw2.y + yw2.y;
                    acc[s][nt][hi] = v0; acc[s][nt][hi + 1] = v1;
                    s1[g] += v0 + v1;
                    s2[g] = fmaf(v0, v0, fmaf(v1, v1, s2[g]));
                }
            }
            float mu[4], rs[4], o2[4];
            #pragma unroll
            for (int g = 0; g < 4; g++) {
                #pragma unroll
                for (int o = 1; o <= 2; o <<= 1) {
                    s1[g] += __shfl_xor_sync(0xffffffffu, s1[g], o);
                    s2[g] += __shfl_xor_sync(0xffffffffu, s2[g], o);
                }
                mu[g] = s1[g] * (1.f / 128.f);
                rs[g] = rsqrtf(s2[g] * (1.f / 128.f) - mu[g] * mu[g] + EPS);
                o2[g] = 0.f;
            }
            #pragma unroll
            for (int nt = 0; nt < 16; nt++) {
                const int h = nt * 8 + 2 * c;
                float2 g2  = *(const float2*)(gm + h);
                float2 be2 = *(const float2*)(be + h);
                float2 w22 = *(const float2*)(w2s + h);
                #pragma unroll
                for (int g = 0; g < 4; g++) {
                    const int s = g >> 1, hi = (g & 1) << 1;
                    float tv;
                    tv = fmaf((acc[s][nt][hi] - mu[g]) * rs[g], g2.x, be2.x);
                    o2[g] = fmaf(fmaxf(tv, 0.f), w22.x, o2[g]);
                    tv = fmaf((acc[s][nt][hi + 1] - mu[g]) * rs[g], g2.y, be2.y);
                    o2[g] = fmaf(fmaxf(tv, 0.f), w22.y, o2[g]);
                }
            }
            #pragma unroll
            for (int g = 0; g < 4; g++) {
                #pragma unroll
                for (int o = 1; o <= 2; o <<= 1)
                    o2[g] += __shfl_xor_sync(0xffffffffu, o2[g], o);
                if (c == 0)
                    out[row + q + 8 * g] = fmaxf(o2[g] + bias2, 0.f);
            }
        }

        __syncthreads();   // all reads of buf[sb] done; prefetch STS visible
    }
}

// ---------------------------------------------------------------------------
extern "C" void kernel_launch(void* const* d_in, const int* in_sizes, int n_in,
                              void* d_out, int out_size)
{
    const float* x     = (const float*)d_in[0];
    const float* y     = (const float*)d_in[1];
    const float* W1    = (const float*)d_in[2];
    const float* b1    = (const float*)d_in[3];
    const float* gamma = (const float*)d_in[4];
    const float* beta  = (const float*)d_in[5];
    const float* W2    = (const float*)d_in[6];
    const float* b2    = (const float*)d_in[7];
    float* out = (float*)d_out;

    cudaFuncSetAttribute(main_kernel,
                         cudaFuncAttributeMaxDynamicSharedMemorySize, SMEM_BYTES);

    precompute_kernel<<<512, 128>>>(x, y, W1, b1);
    main_kernel<<<GRID, THREADS, SMEM_BYTES>>>(x, y, W1, gamma, beta, W2, b2, out);
}